// round 7
// baseline (speedup 1.0000x reference)
#include <cuda_runtime.h>

#define NNODE 21
#define NPAD 24
#define HIDD 128
#define HSTR 132            // padded smem row stride (floats): conflict-free row broadcasts
#define TSTEPS 500
#define NEDGE 210

typedef unsigned long long u64;

// ---------------- packed f32x2 helpers ----------------
__device__ __forceinline__ u64 pk2(float lo, float hi) {
    u64 r; asm("mov.b64 %0,{%1,%2};" : "=l"(r) : "f"(lo), "f"(hi)); return r;
}
__device__ __forceinline__ u64 bc2(float v) {
    u64 r; asm("mov.b64 %0,{%1,%1};" : "=l"(r) : "f"(v)); return r;
}
__device__ __forceinline__ u64 fma2(u64 a, u64 b, u64 c) {
    u64 d; asm("fma.rn.f32x2 %0,%1,%2,%3;" : "=l"(d) : "l"(a), "l"(b), "l"(c)); return d;
}
__device__ __forceinline__ u64 add2(u64 a, u64 b) {
    u64 d; asm("add.rn.f32x2 %0,%1,%2;" : "=l"(d) : "l"(a), "l"(b)); return d;
}
__device__ __forceinline__ void up2(u64 v, float& lo, float& hi) {
    asm("mov.b64 {%0,%1},%2;" : "=f"(lo), "=f"(hi) : "l"(v));
}
__device__ __forceinline__ float sigm(float v) {
    return __fdividef(1.0f, 1.0f + __expf(-v));
}
__device__ __forceinline__ float tanh_(float v) {
    return 1.0f - __fdividef(2.0f, __expf(2.0f * v) + 1.0f);
}

// ---------------- cp.async helpers ----------------
__device__ __forceinline__ void cpa16(void* dst, const void* src) {
    unsigned d = (unsigned)__cvta_generic_to_shared(dst);
    asm volatile("cp.async.cg.shared.global [%0], [%1], 16;\n" :: "r"(d), "l"(src));
}
__device__ __forceinline__ void cpcommit() { asm volatile("cp.async.commit_group;\n"); }
template <int N> __device__ __forceinline__ void cpwait() {
    asm volatile("cp.async.wait_group %0;\n" :: "n"(N));
}

// ---------------- device-global precomputed state ----------------
__device__ float g_A[NNODE * NNODE];
__device__ float g_fold1[6 * HIDD];
__device__ float g_c2[3 * HIDD];
__device__ __align__(16) float g_W2L[3 * HIDD * HIDD];

// ---------------- fused setup kernel ----------------
__global__ void setup_all(
    const int* __restrict__ ei, const float* __restrict__ ew,
    const float* Wz1, const float* bz1, const float* lzw1, const float* lzb1,
    const float* Wr1, const float* br1, const float* lrw1, const float* lrb1,
    const float* Wh1, const float* bh1, const float* lhw1, const float* lhb1,
    const float* Wz2, const float* bz2, const float* lzw2, const float* lzb2,
    const float* Wr2, const float* br2, const float* lrw2, const float* lrb2,
    const float* Wh2, const float* bh2, const float* lhw2, const float* lhb2) {
    int tid = threadIdx.x;
    if (blockIdx.x == 0) {
        __shared__ float dinv[NNODE];
        if (tid < NNODE) {
            float d = 1.0f;
            for (int e = 0; e < NEDGE; e++)
                if (ei[NEDGE + e] == tid) d += ew[e];
            dinv[tid] = (d > 0.f) ? (1.0f / sqrtf(d)) : 0.0f;
        }
        __syncthreads();
        if (tid < NNODE * NNODE) {
            int i = tid / NNODE, j = tid % NNODE;
            float a = (i == j) ? dinv[i] * dinv[i] : 0.0f;
            for (int e = 0; e < NEDGE; e++)
                if (ei[e] == j && ei[NEDGE + e] == i)
                    a += dinv[j] * ew[e] * dinv[i];
            g_A[tid] = a;
        }
        if (tid < HIDD) {
            const float* Ws[3] = {Wz1, Wr1, Wh1};
            const float* bs[3] = {bz1, br1, bh1};
            const float* ls[3] = {lzw1, lrw1, lhw1};
            const float* lb[3] = {lzb1, lrb1, lhb1};
            for (int g = 0; g < 3; g++) {
                float v = 0.f, c = 0.f;
                for (int q = 0; q < HIDD; q++) {
                    float l = ls[g][q * HIDD + tid];
                    v += Ws[g][q] * l;
                    c += bs[g][q] * l;
                }
                g_fold1[g * HIDD + tid] = v;
                g_fold1[(3 + g) * HIDD + tid] = c + lb[g][tid];
            }
            const float* b2[3] = {bz2, br2, bh2};
            const float* l2[3] = {lzw2, lrw2, lhw2};
            const float* p2[3] = {lzb2, lrb2, lhb2};
            for (int g = 0; g < 3; g++) {
                float c = 0.f;
                for (int q = 0; q < HIDD; q++) c += b2[g][q] * l2[g][q * HIDD + tid];
                g_c2[g * HIDD + tid] = c + p2[g][tid];
            }
        }
    } else {
        __shared__ float wrow[HIDD];
        int id = blockIdx.x - 1;
        int g = id >> 7, k = id & 127;
        const float* W = (g == 0) ? Wz2 : ((g == 1) ? Wr2 : Wh2);
        const float* L = (g == 0) ? lzw2 : ((g == 1) ? lrw2 : lhw2);
        if (tid < HIDD) wrow[tid] = W[k * HIDD + tid];
        __syncthreads();
        if (tid < HIDD) {
            float a = 0.f;
            for (int q = 0; q < HIDD; q++) a += wrow[q] * L[q * HIDD + tid];
            g_W2L[g * HIDD * HIDD + k * HIDD + tid] = a;
        }
    }
}

// ---------------- staged-weight split-k matmul ----------------
#define CHUNK_F 4096                  // floats per 32-k chunk of one 128-col matrix
#define NTHR 512

// Stage chunk c of NM matrices into region c. 512 threads, NM*2 cp.async each.
template <int NM>
__device__ __forceinline__ void stage_chunk(float* sw, const float* G0, const float* G1,
                                            int c, int tid) {
    float* reg = sw + c * (NM * CHUNK_F);
    {
        const float* src = G0 + c * CHUNK_F;
        cpa16(reg + tid * 4, src + tid * 4);
        cpa16(reg + 2048 + tid * 4, src + 2048 + tid * 4);
    }
    if (NM > 1) {
        const float* src = G1 + c * CHUNK_F;
        float* dst = reg + CHUNK_F;
        cpa16(dst + tid * 4, src + tid * 4);
        cpa16(dst + 2048 + tid * 4, src + 2048 + tid * 4);
    }
}

// Compute 32 k's from staged region B. Lane owns 3 rows (i0..i0+2) x 4 cols (unit ui).
template <int NM>
__device__ __forceinline__ void mm32(const float* __restrict__ S, int kbase,
                                     const float* __restrict__ B,
                                     int i0, int ui, u64 (&A)[NM][3][2]) {
#pragma unroll 2
    for (int k4 = 0; k4 < 8; k4++) {
        float sa[3][4];
#pragma unroll
        for (int r = 0; r < 3; r++) {
            float4 q = *reinterpret_cast<const float4*>(S + (i0 + r) * HSTR + kbase + k4 * 4);
            sa[r][0] = q.x; sa[r][1] = q.y; sa[r][2] = q.z; sa[r][3] = q.w;
        }
#pragma unroll
        for (int kk = 0; kk < 4; kk++) {
            int k = k4 * 4 + kk;
            ulonglong2 ua, ub;
            ua = *(reinterpret_cast<const ulonglong2*>(B + k * HIDD) + ui);
            if (NM > 1) ub = *(reinterpret_cast<const ulonglong2*>(B + CHUNK_F + k * HIDD) + ui);
#pragma unroll
            for (int r = 0; r < 3; r++) {
                u64 s = bc2(sa[r][kk]);
                A[0][r][0] = fma2(s, ua.x, A[0][r][0]);
                A[0][r][1] = fma2(s, ua.y, A[0][r][1]);
                if (NM > 1) {
                    A[1][r][0] = fma2(s, ub.x, A[1][r][0]);
                    A[1][r][1] = fma2(s, ub.y, A[1][r][1]);
                }
            }
        }
    }
}

// Full split-k pass. kh0 (warps 0-7) reduces k[0,64), kh1 (warps 8-15) k[64,128).
// After return, kh0 lanes hold the full k-sum in A; kh1 lanes' A is consumed.
template <int NM>
__device__ __forceinline__ void run_pass(const float* __restrict__ S,
                                         const float* G0, const float* G1,
                                         float* sw, int tid, int kh, int i0, int ui,
                                         u64 (&A)[NM][3][2]) {
    __syncthreads();   // #0: prev scratch reads + prev epilogue writes done before restaging
    stage_chunk<NM>(sw, G0, G1, 0, tid);
    stage_chunk<NM>(sw, G0, G1, 2, tid);
    cpcommit();
    stage_chunk<NM>(sw, G0, G1, 1, tid);
    stage_chunk<NM>(sw, G0, G1, 3, tid);
    cpcommit();
    const int cA = kh * 2, cB = kh * 2 + 1;
    cpwait<1>();
    __syncthreads();   // #1: chunks {0,2} resident
    mm32<NM>(S, cA * 32, sw + cA * (NM * CHUNK_F), i0, ui, A);
    cpwait<0>();
    __syncthreads();   // #2: chunks {1,3} resident; region A reads finished
    mm32<NM>(S, cB * 32, sw + cB * (NM * CHUNK_F), i0, ui, A);
    // k-reduction through scratch aliased to region 0 (free: all reads done pre-#2)
    const int SSTR = NM * 6 + 1;   // u64 stride, odd -> low bank conflict
    if (kh == 1) {
        u64* scr = reinterpret_cast<u64*>(sw) + (tid - 256) * SSTR;
#pragma unroll
        for (int m = 0; m < NM; m++)
#pragma unroll
            for (int r = 0; r < 3; r++) {
                scr[m * 6 + r * 2] = A[m][r][0];
                scr[m * 6 + r * 2 + 1] = A[m][r][1];
            }
    }
    __syncthreads();   // #3: partials visible
    if (kh == 0) {
        const u64* scr = reinterpret_cast<const u64*>(sw) + tid * SSTR;
#pragma unroll
        for (int m = 0; m < NM; m++)
#pragma unroll
            for (int r = 0; r < 3; r++) {
                A[m][r][0] = add2(A[m][r][0], scr[m * 6 + r * 2]);
                A[m][r][1] = add2(A[m][r][1], scr[m * 6 + r * 2 + 1]);
            }
    }
}

// A-mix over node range [j0,j1): acc += A[i,j] * M[j,:]
template <int NM>
__device__ __forceinline__ void amixN(const float* __restrict__ sA,
                                      const float* __restrict__ M0,
                                      const float* __restrict__ M1,
                                      int j0, int j1, int i0, int ui, u64 (&A)[NM][3][2]) {
    const ulonglong2* Ma = reinterpret_cast<const ulonglong2*>(M0);
    const ulonglong2* Mb = reinterpret_cast<const ulonglong2*>(M1);
    for (int j = j0; j < j1; j++) {
        ulonglong2 ma = Ma[j * (HSTR / 4) + ui];
        ulonglong2 mb;
        if (NM > 1) mb = Mb[j * (HSTR / 4) + ui];
#pragma unroll
        for (int r = 0; r < 3; r++) {
            u64 a = bc2(sA[(i0 + r) * NNODE + j]);
            A[0][r][0] = fma2(a, ma.x, A[0][r][0]);
            A[0][r][1] = fma2(a, ma.y, A[0][r][1]);
            if (NM > 1) {
                A[1][r][0] = fma2(a, mb.x, A[1][r][0]);
                A[1][r][1] = fma2(a, mb.y, A[1][r][1]);
            }
        }
    }
}

// ---------------- main persistent kernel: one CTA per batch element ----------------
#define BIG (NPAD * HSTR)                                     // 3168 floats per state array
#define STAGE_F (4 * 2 * CHUNK_F)                             // 4 chunks x NM<=2 = 32768 floats
#define SMEM_FLOATS (7 * BIG + 504 + 32 + 9 * HIDD + STAGE_F) // 56632 floats = 226528 B

__global__ void __launch_bounds__(NTHR, 1) tgcn_main(
    const float* __restrict__ x,
    const float* __restrict__ Uz1, const float* __restrict__ Ur1, const float* __restrict__ Uh1,
    const float* __restrict__ Uz2, const float* __restrict__ Ur2, const float* __restrict__ Uh2,
    const float* __restrict__ clsw, const float* __restrict__ clsb,
    float* __restrict__ out) {
    extern __shared__ float sm[];
    float* sH1 = sm;
    float* sH2 = sH1 + BIG;
    float* sZ  = sH2 + BIG;
    float* sHR = sZ  + BIG;
    float* sMa = sHR + BIG;
    float* sMb = sMa + BIG;
    float* sMc = sMb + BIG;
    float* sA  = sMc + BIG;            // 504 (24x21)
    float* sy  = sA + 504;             // 32
    float* sv  = sy + 32;              // 9 * 128
    float* sw  = sv + 9 * HIDD;        // stage buffers / reduction scratch
    float* svz = sv,         *svr = sv + 128, *svh = sv + 256;
    float* scz = sv + 384,   *scr = sv + 512, *sch = sv + 640;
    float* sc2z = sv + 768,  *sc2r = sv + 896, *sc2h = sv + 1024;

    const int tid = threadIdx.x, b = blockIdx.x;
    const int w = tid >> 5, lane = tid & 31;
    const int kh = w >> 3;              // k-half: 0 -> k[0,64), 1 -> k[64,128)
    const int wc = w & 7;               // col-warp (16 cols each)
    const int fg = lane & 3, rg = lane >> 2;
    const int ui = wc * 4 + fg;         // 16B unit (4 cols) this lane owns
    const int f0 = ui * 4;
    const int i0 = rg * 3;              // 3 rows (rows 21-23 padding at rg==7)

    for (int i = tid; i < BIG; i += NTHR) { sH1[i] = 0.f; sH2[i] = 0.f; }
    for (int i = tid; i < 504; i += NTHR) sA[i] = (i < NNODE * NNODE) ? g_A[i] : 0.f;
    if (tid < 32) sy[tid] = 0.f;
    if (tid < HIDD)
        for (int g = 0; g < 9; g++)
            sv[g * 128 + tid] = (g < 6) ? g_fold1[g * 128 + tid] : g_c2[(g - 6) * 128 + tid];
    __syncthreads();

    float accS[12];
#pragma unroll
    for (int q = 0; q < 12; q++) accS[q] = 0.f;

    const float* xb = x + (size_t)b * TSTEPS * NNODE;
    const float* W2Lz = g_W2L;
    const float* W2Lr = g_W2L + HIDD * HIDD;
    const float* W2Lh = g_W2L + 2 * HIDD * HIDD;

    for (int t = 0; t < TSTEPS; t++) {
        // y = A @ x_t (warp 0 threads; consumed after run_pass sync #3)
        if (tid < NNODE) {
            const float* xr = xb + t * NNODE;
            float a = 0.f;
#pragma unroll
            for (int j = 0; j < NNODE; j++) a += sA[tid * NNODE + j] * xr[j];
            sy[tid] = a;
        }

        // ---- P1: Z1, R1 ----
        {
            u64 A[2][3][2] = {};
            run_pass<2>(sH1, Uz1, Ur1, sw, tid, kh, i0, ui, A);
            if (tid < 256) {
#pragma unroll
                for (int r = 0; r < 3; r++) {
                    int i = i0 + r; float yv = sy[i];
                    float v[4], q[4];
                    up2(A[0][r][0], v[0], v[1]); up2(A[0][r][1], v[2], v[3]);
                    up2(A[1][r][0], q[0], q[1]); up2(A[1][r][1], q[2], q[3]);
                    float4 h4 = *reinterpret_cast<const float4*>(sH1 + i * HSTR + f0);
                    float h[4] = {h4.x, h4.y, h4.z, h4.w};
                    float zz[4], rr[4];
#pragma unroll
                    for (int c = 0; c < 4; c++) {
                        int f = f0 + c;
                        zz[c] = sigm(fmaf(yv, svz[f], scz[f]) + v[c]);
                        rr[c] = sigm(fmaf(yv, svr[f], scr[f]) + q[c]) * h[c];
                    }
                    *reinterpret_cast<float4*>(sZ + i * HSTR + f0) = make_float4(zz[0], zz[1], zz[2], zz[3]);
                    *reinterpret_cast<float4*>(sHR + i * HSTR + f0) = make_float4(rr[0], rr[1], rr[2], rr[3]);
                }
            }
        }

        // ---- P2: Ht1 + blend into H1 ----
        {
            u64 A[1][3][2] = {};
            run_pass<1>(sHR, Uh1, nullptr, sw, tid, kh, i0, ui, A);
            if (tid < 256) {
#pragma unroll
                for (int r = 0; r < 3; r++) {
                    int i = i0 + r; float yv = sy[i];
                    float v[4];
                    up2(A[0][r][0], v[0], v[1]); up2(A[0][r][1], v[2], v[3]);
                    float4 h4 = *reinterpret_cast<const float4*>(sH1 + i * HSTR + f0);
                    float4 z4 = *reinterpret_cast<const float4*>(sZ + i * HSTR + f0);
                    float h[4] = {h4.x, h4.y, h4.z, h4.w};
                    float z[4] = {z4.x, z4.y, z4.z, z4.w};
                    float nh[4];
#pragma unroll
                    for (int c = 0; c < 4; c++) {
                        int f = f0 + c;
                        float hh = tanh_(fmaf(yv, svh[f], sch[f]) + v[c]);
                        nh[c] = fmaf(z[c], h[c] - hh, hh);
                    }
                    *reinterpret_cast<float4*>(sH1 + i * HSTR + f0) = make_float4(nh[0], nh[1], nh[2], nh[3]);
                }
            }
        }

        // ---- P3: Mz, Mr = H1 @ W2L{z,r} ----
        {
            u64 A[2][3][2] = {};
            run_pass<2>(sH1, W2Lz, W2Lr, sw, tid, kh, i0, ui, A);
            if (tid < 256) {
#pragma unroll
                for (int r = 0; r < 3; r++) {
                    int i = i0 + r;
                    float a[4], bq[4];
                    up2(A[0][r][0], a[0], a[1]); up2(A[0][r][1], a[2], a[3]);
                    up2(A[1][r][0], bq[0], bq[1]); up2(A[1][r][1], bq[2], bq[3]);
                    *reinterpret_cast<float4*>(sMa + i * HSTR + f0) = make_float4(a[0], a[1], a[2], a[3]);
                    *reinterpret_cast<float4*>(sMb + i * HSTR + f0) = make_float4(bq[0], bq[1], bq[2], bq[3]);
                }
            }
        }

        // ---- P4: Mh = H1 @ W2Lh ----
        {
            u64 A[1][3][2] = {};
            run_pass<1>(sH1, W2Lh, nullptr, sw, tid, kh, i0, ui, A);
            if (tid < 256) {
#pragma unroll
                for (int r = 0; r < 3; r++) {
                    int i = i0 + r;
                    float a[4];
                    up2(A[0][r][0], a[0], a[1]); up2(A[0][r][1], a[2], a[3]);
                    *reinterpret_cast<float4*>(sMc + i * HSTR + f0) = make_float4(a[0], a[1], a[2], a[3]);
                }
            }
        }

        // ---- P5: Z2 / R2 (bias + split amix + H2 matmul) ----
        {
            u64 A[2][3][2];
            if (kh == 0) {
                u64 cz0 = pk2(sc2z[f0], sc2z[f0 + 1]), cz1 = pk2(sc2z[f0 + 2], sc2z[f0 + 3]);
                u64 cr0 = pk2(sc2r[f0], sc2r[f0 + 1]), cr1 = pk2(sc2r[f0 + 2], sc2r[f0 + 3]);
#pragma unroll
                for (int r = 0; r < 3; r++) {
                    A[0][r][0] = cz0; A[0][r][1] = cz1;
                    A[1][r][0] = cr0; A[1][r][1] = cr1;
                }
                amixN<2>(sA, sMa, sMb, 0, 11, i0, ui, A);
            } else {
#pragma unroll
                for (int r = 0; r < 3; r++) {
                    A[0][r][0] = 0; A[0][r][1] = 0;
                    A[1][r][0] = 0; A[1][r][1] = 0;
                }
                amixN<2>(sA, sMa, sMb, 11, NNODE, i0, ui, A);
            }
            run_pass<2>(sH2, Uz2, Ur2, sw, tid, kh, i0, ui, A);
            if (tid < 256) {
#pragma unroll
                for (int r = 0; r < 3; r++) {
                    int i = i0 + r;
                    float v[4], q[4];
                    up2(A[0][r][0], v[0], v[1]); up2(A[0][r][1], v[2], v[3]);
                    up2(A[1][r][0], q[0], q[1]); up2(A[1][r][1], q[2], q[3]);
                    float4 h4 = *reinterpret_cast<const float4*>(sH2 + i * HSTR + f0);
                    float h[4] = {h4.x, h4.y, h4.z, h4.w};
                    float zz[4], rr[4];
#pragma unroll
                    for (int c = 0; c < 4; c++) {
                        zz[c] = sigm(v[c]);
                        rr[c] = sigm(q[c]) * h[c];
                    }
                    *reinterpret_cast<float4*>(sZ + i * HSTR + f0) = make_float4(zz[0], zz[1], zz[2], zz[3]);
                    *reinterpret_cast<float4*>(sHR + i * HSTR + f0) = make_float4(rr[0], rr[1], rr[2], rr[3]);
                }
            }
        }

        // ---- P6: Ht2 + blend into H2 + output accumulation ----
        {
            u64 A[1][3][2];
            if (kh == 0) {
                u64 ch0 = pk2(sc2h[f0], sc2h[f0 + 1]), ch1 = pk2(sc2h[f0 + 2], sc2h[f0 + 3]);
#pragma unroll
                for (int r = 0; r < 3; r++) { A[0][r][0] = ch0; A[0][r][1] = ch1; }
                amixN<1>(sA, sMc, nullptr, 0, 11, i0, ui, A);
            } else {
#pragma unroll
                for (int r = 0; r < 3; r++) { A[0][r][0] = 0; A[0][r][1] = 0; }
                amixN<1>(sA, sMc, nullptr, 11, NNODE, i0, ui, A);
            }
            run_pass<1>(sHR, Uh2, nullptr, sw, tid, kh, i0, ui, A);
            if (tid < 256) {
#pragma unroll
                for (int r = 0; r < 3; r++) {
                    int i = i0 + r;
                    float v[4];
                    up2(A[0][r][0], v[0], v[1]); up2(A[0][r][1], v[2], v[3]);
                    float4 h4 = *reinterpret_cast<const float4*>(sH2 + i * HSTR + f0);
                    float4 z4 = *reinterpret_cast<const float4*>(sZ + i * HSTR + f0);
                    float h[4] = {h4.x, h4.y, h4.z, h4.w};
                    float z[4] = {z4.x, z4.y, z4.z, z4.w};
                    float nh[4];
#pragma unroll
                    for (int c = 0; c < 4; c++) {
                        float hh = tanh_(v[c]);
                        nh[c] = fmaf(z[c], h[c] - hh, hh);
                        if (rg < 7) accS[r * 4 + c] += nh[c];
                    }
                    *reinterpret_cast<float4*>(sH2 + i * HSTR + f0) = make_float4(nh[0], nh[1], nh[2], nh[3]);
                }
            }
        }
    }

    // ---- final: out[b] = (sum over nodes,time / (21*500)) @ cls_w + cls_b ----
    __syncthreads();
    if (tid < 256 && rg < 7) {
        float cs[4];
#pragma unroll
        for (int c = 0; c < 4; c++) cs[c] = accS[c] + accS[4 + c] + accS[8 + c];
        *reinterpret_cast<float4*>(sMa + rg * HIDD + f0) = make_float4(cs[0], cs[1], cs[2], cs[3]);
    }
    __syncthreads();
    if (tid < HIDD) {
        float s = 0.f;
#pragma unroll
        for (int r = 0; r < 7; r++) s += sMa[r * HIDD + tid];
        s *= (1.0f / (float)(NNODE * TSTEPS));
        sMb[tid] = s * clsw[tid];
    }
    __syncthreads();
    if (tid == 0) {
        float s = 0.f;
        for (int f = 0; f < HIDD; f++) s += sMb[f];
        out[b] = s + clsb[0];
    }
}

// ---------------- launch ----------------
extern "C" void kernel_launch(void* const* d_in, const int* in_sizes, int n_in,
                              void* d_out, int out_size) {
    const float* x    = (const float*)d_in[0];
    const int*   ei   = (const int*)d_in[1];
    const float* ew   = (const float*)d_in[2];
    const float* Wz1  = (const float*)d_in[3];
    const float* bz1  = (const float*)d_in[4];
    const float* lzw1 = (const float*)d_in[5];
    const float* lzb1 = (const float*)d_in[6];
    const float* Wr1  = (const float*)d_in[7];
    const float* br1  = (const float*)d_in[8];
    const float* lrw1 = (const float*)d_in[9];
    const float* lrb1 = (const float*)d_in[10];
    const float* Wh1  = (const float*)d_in[11];
    const float* bh1  = (const float*)d_in[12];
    const float* lhw1 = (const float*)d_in[13];
    const float* lhb1 = (const float*)d_in[14];
    const float* Wz2  = (const float*)d_in[15];
    const float* bz2  = (const float*)d_in[16];
    const float* lzw2 = (const float*)d_in[17];
    const float* lzb2 = (const float*)d_in[18];
    const float* Wr2  = (const float*)d_in[19];
    const float* br2  = (const float*)d_in[20];
    const float* lrw2 = (const float*)d_in[21];
    const float* lrb2 = (const float*)d_in[22];
    const float* Wh2  = (const float*)d_in[23];
    const float* bh2  = (const float*)d_in[24];
    const float* lhw2 = (const float*)d_in[25];
    const float* lhb2 = (const float*)d_in[26];
    const float* clsw = (const float*)d_in[27];
    const float* clsb = (const float*)d_in[28];
    float* out = (float*)d_out;

    setup_all<<<385, 448>>>(ei, ew,
        Wz1, bz1, lzw1, lzb1, Wr1, br1, lrw1, lrb1, Wh1, bh1, lhw1, lhb1,
        Wz2, bz2, lzw2, lzb2, Wr2, br2, lrw2, lrb2, Wh2, bh2, lhw2, lhb2);

    const int smem_bytes = SMEM_FLOATS * (int)sizeof(float);  // 226528
    cudaFuncSetAttribute(tgcn_main, cudaFuncAttributeMaxDynamicSharedMemorySize, smem_bytes);
    tgcn_main<<<64, NTHR, smem_bytes>>>(
        x,
        lzw1 + HIDD * HIDD, lrw1 + HIDD * HIDD, lhw1 + HIDD * HIDD,
        lzw2 + HIDD * HIDD, lrw2 + HIDD * HIDD, lhw2 + HIDD * HIDD,
        clsw, clsb, out);
}

// round 9
// speedup vs baseline: 1.4500x; 1.4500x over previous
#include <cuda_runtime.h>
#include <cstdint>

#define NNODE 21
#define NPAD 24
#define HIDD 128
#define HSTR 132            // padded smem row stride (floats): conflict-free row broadcasts
#define TSTEPS 500
#define NEDGE 210
#define NTHR 256
#define FHALF 64            // features per CTA (cluster of 2)

typedef unsigned long long u64;
typedef unsigned int u32;

// ---------------- packed f32x2 helpers ----------------
__device__ __forceinline__ u64 pk2(float lo, float hi) {
    u64 r; asm("mov.b64 %0,{%1,%2};" : "=l"(r) : "f"(lo), "f"(hi)); return r;
}
__device__ __forceinline__ u64 bc2(float v) {
    u64 r; asm("mov.b64 %0,{%1,%1};" : "=l"(r) : "f"(v)); return r;
}
__device__ __forceinline__ u64 fma2(u64 a, u64 b, u64 c) {
    u64 d; asm("fma.rn.f32x2 %0,%1,%2,%3;" : "=l"(d) : "l"(a), "l"(b), "l"(c)); return d;
}
__device__ __forceinline__ u64 add2(u64 a, u64 b) {
    u64 d; asm("add.rn.f32x2 %0,%1,%2;" : "=l"(d) : "l"(a), "l"(b)); return d;
}
__device__ __forceinline__ void up2(u64 v, float& lo, float& hi) {
    asm("mov.b64 {%0,%1},%2;" : "=f"(lo), "=f"(hi) : "l"(v));
}
__device__ __forceinline__ float sigm(float v) {
    return __fdividef(1.0f, 1.0f + __expf(-v));
}
__device__ __forceinline__ float tanh_(float v) {
    return 1.0f - __fdividef(2.0f, __expf(2.0f * v) + 1.0f);
}

// ---------------- cp.async helpers ----------------
__device__ __forceinline__ void cpa16(void* dst, const void* src) {
    u32 d = (u32)__cvta_generic_to_shared(dst);
    asm volatile("cp.async.cg.shared.global [%0], [%1], 16;\n" :: "r"(d), "l"(src));
}
__device__ __forceinline__ void cpcommit() { asm volatile("cp.async.commit_group;\n"); }
template <int N> __device__ __forceinline__ void cpwait() {
    asm volatile("cp.async.wait_group %0;\n" :: "n"(N));
}

// ---------------- cluster helpers ----------------
#define CLUSTER_ARRIVE() asm volatile("barrier.cluster.arrive.aligned;" ::: "memory")
#define CLUSTER_WAIT()   asm volatile("barrier.cluster.wait.aligned;" ::: "memory")

__device__ __forceinline__ u32 ctarank() {
    u32 r; asm("mov.u32 %0, %%cluster_ctarank;" : "=r"(r)); return r;
}
__device__ __forceinline__ void st_peer_u64(u32 laddr, u32 peer, u64 v) {
    u32 raddr;
    asm("mapa.shared::cluster.u32 %0, %1, %2;" : "=r"(raddr) : "r"(laddr), "r"(peer));
    asm volatile("st.shared::cluster.b64 [%0], %1;" :: "r"(raddr), "l"(v) : "memory");
}
__device__ __forceinline__ void st_peer_u32(u32 laddr, u32 peer, u32 v) {
    u32 raddr;
    asm("mapa.shared::cluster.u32 %0, %1, %2;" : "=r"(raddr) : "r"(laddr), "r"(peer));
    asm volatile("st.shared::cluster.b32 [%0], %1;" :: "r"(raddr), "r"(v) : "memory");
}
__device__ __forceinline__ u32 smem_u32(const void* p) {
    return (u32)__cvta_generic_to_shared(p);
}

// ---------------- device-global precomputed state ----------------
__device__ float g_A[NNODE * NNODE];
__device__ float g_fold1[6 * HIDD];
__device__ float g_c2[3 * HIDD];
__device__ __align__(16) float g_W2L[3 * HIDD * HIDD];

// ---------------- fused setup kernel ----------------
__global__ void setup_all(
    const int* __restrict__ ei, const float* __restrict__ ew,
    const float* Wz1, const float* bz1, const float* lzw1, const float* lzb1,
    const float* Wr1, const float* br1, const float* lrw1, const float* lrb1,
    const float* Wh1, const float* bh1, const float* lhw1, const float* lhb1,
    const float* Wz2, const float* bz2, const float* lzw2, const float* lzb2,
    const float* Wr2, const float* br2, const float* lrw2, const float* lrb2,
    const float* Wh2, const float* bh2, const float* lhw2, const float* lhb2) {
    int tid = threadIdx.x;
    if (blockIdx.x == 0) {
        __shared__ float dinv[NNODE];
        if (tid < NNODE) {
            float d = 1.0f;
            for (int e = 0; e < NEDGE; e++)
                if (ei[NEDGE + e] == tid) d += ew[e];
            dinv[tid] = (d > 0.f) ? (1.0f / sqrtf(d)) : 0.0f;
        }
        __syncthreads();
        if (tid < NNODE * NNODE) {
            int i = tid / NNODE, j = tid % NNODE;
            float a = (i == j) ? dinv[i] * dinv[i] : 0.0f;
            for (int e = 0; e < NEDGE; e++)
                if (ei[e] == j && ei[NEDGE + e] == i)
                    a += dinv[j] * ew[e] * dinv[i];
            g_A[tid] = a;
        }
        if (tid < HIDD) {
            const float* Ws[3] = {Wz1, Wr1, Wh1};
            const float* bs[3] = {bz1, br1, bh1};
            const float* ls[3] = {lzw1, lrw1, lhw1};
            const float* lb[3] = {lzb1, lrb1, lhb1};
            for (int g = 0; g < 3; g++) {
                float v = 0.f, c = 0.f;
                for (int q = 0; q < HIDD; q++) {
                    float l = ls[g][q * HIDD + tid];
                    v += Ws[g][q] * l;
                    c += bs[g][q] * l;
                }
                g_fold1[g * HIDD + tid] = v;
                g_fold1[(3 + g) * HIDD + tid] = c + lb[g][tid];
            }
            const float* b2[3] = {bz2, br2, bh2};
            const float* l2[3] = {lzw2, lrw2, lhw2};
            const float* p2[3] = {lzb2, lrb2, lhb2};
            for (int g = 0; g < 3; g++) {
                float c = 0.f;
                for (int q = 0; q < HIDD; q++) c += b2[g][q] * l2[g][q * HIDD + tid];
                g_c2[g * HIDD + tid] = c + p2[g][tid];
            }
        }
    } else {
        __shared__ float wrow[HIDD];
        int id = blockIdx.x - 1;
        int g = id >> 7, k = id & 127;
        const float* W = (g == 0) ? Wz2 : ((g == 1) ? Wr2 : Wh2);
        const float* L = (g == 0) ? lzw2 : ((g == 1) ? lrw2 : lhw2);
        if (tid < HIDD) wrow[tid] = W[k * HIDD + tid];
        __syncthreads();
        if (tid < HIDD) {
            float a = 0.f;
            for (int q = 0; q < HIDD; q++) a += wrow[q] * L[q * HIDD + tid];
            g_W2L[g * HIDD * HIDD + k * HIDD + tid] = a;
        }
    }
}

// ---------------- staged-weight split-k matmul (64-col half) ----------------
#define CHUNK_F 2048                  // floats per 32-k x 64-col chunk

// Stage chunk c (32 k rows, this CTA's 64 cols) of NM matrices into slot c.
// G pointers are pre-offset by rank*64 columns; gmem row stride = 128.
template <int NM>
__device__ __forceinline__ void stage_chunk(float* sw, const float* G0, const float* G1,
                                            int c, int tid) {
    int e = tid * 8;
    int row = e >> 6, col = e & 63;
    long off = (long)(c * 32 + row) * HIDD + col;
    float* reg = sw + c * (NM * CHUNK_F);
    cpa16(reg + e, G0 + off);
    cpa16(reg + e + 4, G0 + off + 4);
    if (NM > 1) {
        cpa16(reg + CHUNK_F + e, G1 + off);
        cpa16(reg + CHUNK_F + e + 4, G1 + off + 4);
    }
}

// Compute 32 k's from staged slot B ([k 32][col 64] floats).
template <int NM>
__device__ __forceinline__ void mm32(const float* __restrict__ S, int kbase,
                                     const float* __restrict__ B,
                                     int i0, int ui, u64 (&A)[NM][3][2]) {
#pragma unroll 2
    for (int k4 = 0; k4 < 8; k4++) {
        float sa[3][4];
#pragma unroll
        for (int r = 0; r < 3; r++) {
            float4 q = *reinterpret_cast<const float4*>(S + (i0 + r) * HSTR + kbase + k4 * 4);
            sa[r][0] = q.x; sa[r][1] = q.y; sa[r][2] = q.z; sa[r][3] = q.w;
        }
#pragma unroll
        for (int kk = 0; kk < 4; kk++) {
            int k = k4 * 4 + kk;
            ulonglong2 ua, ub;
            ua = *(reinterpret_cast<const ulonglong2*>(B) + k * 16 + ui);
            if (NM > 1) ub = *(reinterpret_cast<const ulonglong2*>(B + CHUNK_F) + k * 16 + ui);
#pragma unroll
            for (int r = 0; r < 3; r++) {
                u64 s = bc2(sa[r][kk]);
                A[0][r][0] = fma2(s, ua.x, A[0][r][0]);
                A[0][r][1] = fma2(s, ua.y, A[0][r][1]);
                if (NM > 1) {
                    A[1][r][0] = fma2(s, ub.x, A[1][r][0]);
                    A[1][r][1] = fma2(s, ub.y, A[1][r][1]);
                }
            }
        }
    }
}

// Full split-k pass. kh0 (warps 0-3) reduces k[0,64), kh1 (warps 4-7) k[64,128).
// After return, kh0 lanes (tid<128) hold the full k-sum in A.
template <int NM>
__device__ __forceinline__ void run_pass(const float* __restrict__ S,
                                         const float* G0, const float* G1,
                                         float* sw, int tid, int kh, int i0, int ui,
                                         u64 (&A)[NM][3][2]) {
    __syncthreads();   // #0: prev scratch/slot reads + prev epilogue writes done
    stage_chunk<NM>(sw, G0, G1, 0, tid);
    stage_chunk<NM>(sw, G0, G1, 2, tid);
    cpcommit();
    stage_chunk<NM>(sw, G0, G1, 1, tid);
    stage_chunk<NM>(sw, G0, G1, 3, tid);
    cpcommit();
    const int cA = kh * 2, cB = kh * 2 + 1;
    cpwait<1>();
    __syncthreads();   // #1: chunks {0,2} resident
    mm32<NM>(S, cA * 32, sw + cA * (NM * CHUNK_F), i0, ui, A);
    cpwait<0>();
    __syncthreads();   // #2: chunks {1,3} resident; slot-0/2 reads finished
    mm32<NM>(S, cB * 32, sw + cB * (NM * CHUNK_F), i0, ui, A);
    // k-reduction through scratch aliased to slot 0 (reads done pre-#2)
    const int SSTR = NM * 6 + 1;
    if (kh == 1) {
        u64* scr = reinterpret_cast<u64*>(sw) + (tid - 128) * SSTR;
#pragma unroll
        for (int m = 0; m < NM; m++)
#pragma unroll
            for (int r = 0; r < 3; r++) {
                scr[m * 6 + r * 2] = A[m][r][0];
                scr[m * 6 + r * 2 + 1] = A[m][r][1];
            }
    }
    __syncthreads();   // #3: partials visible
    if (kh == 0) {
        const u64* scr = reinterpret_cast<const u64*>(sw) + tid * SSTR;
#pragma unroll
        for (int m = 0; m < NM; m++)
#pragma unroll
            for (int r = 0; r < 3; r++) {
                A[m][r][0] = add2(A[m][r][0], scr[m * 6 + r * 2]);
                A[m][r][1] = add2(A[m][r][1], scr[m * 6 + r * 2 + 1]);
            }
    }
}

// A-mix over node range [j0,j1): acc += A[i,j] * M[j, local cols]
template <int NM>
__device__ __forceinline__ void amixN(const float* __restrict__ sA,
                                      const float* __restrict__ M0,
                                      const float* __restrict__ M1,
                                      int j0, int j1, int i0, int ui, u64 (&A)[NM][3][2]) {
    const ulonglong2* Ma = reinterpret_cast<const ulonglong2*>(M0);
    const ulonglong2* Mb = reinterpret_cast<const ulonglong2*>(M1);
    for (int j = j0; j < j1; j++) {
        ulonglong2 ma = Ma[j * (HSTR / 4) + ui];
        ulonglong2 mb;
        if (NM > 1) mb = Mb[j * (HSTR / 4) + ui];
#pragma unroll
        for (int r = 0; r < 3; r++) {
            u64 a = bc2(sA[(i0 + r) * NNODE + j]);
            A[0][r][0] = fma2(a, ma.x, A[0][r][0]);
            A[0][r][1] = fma2(a, ma.y, A[0][r][1]);
            if (NM > 1) {
                A[1][r][0] = fma2(a, mb.x, A[1][r][0]);
                A[1][r][1] = fma2(a, mb.y, A[1][r][1]);
            }
        }
    }
}

// ---------------- main kernel: 2-CTA cluster per batch element ----------------
#define BIG (NPAD * HSTR)                                     // 3168 floats per state array
#define STAGE_F (4 * 2 * CHUNK_F)                             // 4 slots x NM<=2 = 16384 floats
#define SMEM_FLOATS (7 * BIG + 504 + 32 + 9 * HIDD + STAGE_F) // 40248 floats = 160992 B

__global__ void __launch_bounds__(NTHR, 1) __cluster_dims__(2, 1, 1) tgcn_main(
    const float* __restrict__ x,
    const float* __restrict__ Uz1, const float* __restrict__ Ur1, const float* __restrict__ Uh1,
    const float* __restrict__ Uz2, const float* __restrict__ Ur2, const float* __restrict__ Uh2,
    const float* __restrict__ clsw, const float* __restrict__ clsb,
    float* __restrict__ out) {
    extern __shared__ float sm[];
    float* sH1 = sm;              // full 128-col state (global feature index)
    float* sH2 = sH1 + BIG;       // full
    float* sZ  = sH2 + BIG;       // own half used (global index)
    float* sHR = sZ  + BIG;       // full
    float* sMa = sHR + BIG;       // own half (local cols 0..63)
    float* sMb = sMa + BIG;
    float* sMc = sMb + BIG;
    float* sA  = sMc + BIG;       // 504 (24x21)
    float* sy  = sA + 504;        // 32 (21 used; [24] = peer partial scratch)
    float* sv  = sy + 32;         // 9 * 128 (global feature index)
    float* sw  = sv + 9 * HIDD;   // stage slots / reduction scratch
    float* svz = sv,         *svr = sv + 128, *svh = sv + 256;
    float* scz = sv + 384,   *scr = sv + 512, *sch = sv + 640;
    float* sc2z = sv + 768,  *sc2r = sv + 896, *sc2h = sv + 1024;

    const int tid = threadIdx.x;
    const u32 rank = ctarank(), peer = 1 - rank;
    const int b = blockIdx.x >> 1;
    const int w = tid >> 5, lane = tid & 31;
    const int kh = w >> 2;              // k-half: warps 0-3 k[0,64), warps 4-7 k[64,128)
    const int wc = w & 3;               // col-warp (16 local cols each)
    const int fg = lane & 3, rg = lane >> 2;
    const int ui = wc * 4 + fg;         // local 16B unit, [0,16)
    const int f0 = ui * 4;              // local col [0,64)
    const int fgl = rank * FHALF + f0;  // global feature col
    const int i0 = rg * 3;              // 3 rows (rows 21-23 padding at rg==7)

    for (int i = tid; i < BIG; i += NTHR) { sH1[i] = 0.f; sH2[i] = 0.f; }
    for (int i = tid; i < 504; i += NTHR) sA[i] = (i < NNODE * NNODE) ? g_A[i] : 0.f;
    if (tid < 32) sy[tid] = 0.f;
    if (tid < HIDD)
        for (int g = 0; g < 9; g++)
            sv[g * 128 + tid] = (g < 6) ? g_fold1[g * 128 + tid] : g_c2[(g - 6) * 128 + tid];
    __syncthreads();
    CLUSTER_ARRIVE();                    // gen 0: init done

    float accS[12];
#pragma unroll
    for (int q = 0; q < 12; q++) accS[q] = 0.f;

    const float* xb = x + (size_t)b * TSTEPS * NNODE;
    // weight pointers pre-offset to this CTA's column half
    const float* W2Lz = g_W2L + rank * FHALF;
    const float* W2Lr = g_W2L + HIDD * HIDD + rank * FHALF;
    const float* W2Lh = g_W2L + 2 * HIDD * HIDD + rank * FHALF;
    const float* Vz1 = Uz1 + rank * FHALF;
    const float* Vr1 = Ur1 + rank * FHALF;
    const float* Vh1 = Uh1 + rank * FHALF;
    const float* Vz2 = Uz2 + rank * FHALF;
    const float* Vr2 = Ur2 + rank * FHALF;
    const float* Vh2 = Uh2 + rank * FHALF;

    for (int t = 0; t < TSTEPS; t++) {
        CLUSTER_WAIT();                  // peer finished prev step (H2/HR hazards)

        // y = A @ x_t
        if (tid < NNODE) {
            const float* xr = xb + t * NNODE;
            float a = 0.f;
#pragma unroll
            for (int j = 0; j < NNODE; j++) a += sA[tid * NNODE + j] * xr[j];
            sy[tid] = a;
        }

        // ---- P1: Z1, R1 (S = full H1) ----
        {
            u64 A[2][3][2] = {};
            run_pass<2>(sH1, Vz1, Vr1, sw, tid, kh, i0, ui, A);
            if (tid < 128) {
#pragma unroll
                for (int r = 0; r < 3; r++) {
                    int i = i0 + r; float yv = sy[i];
                    float v[4], q[4];
                    up2(A[0][r][0], v[0], v[1]); up2(A[0][r][1], v[2], v[3]);
                    up2(A[1][r][0], q[0], q[1]); up2(A[1][r][1], q[2], q[3]);
                    float4 h4 = *reinterpret_cast<const float4*>(sH1 + i * HSTR + fgl);
                    float h[4] = {h4.x, h4.y, h4.z, h4.w};
                    float zz[4], rr[4];
#pragma unroll
                    for (int c = 0; c < 4; c++) {
                        int f = fgl + c;
                        zz[c] = sigm(fmaf(yv, svz[f], scz[f]) + v[c]);
                        rr[c] = sigm(fmaf(yv, svr[f], scr[f]) + q[c]) * h[c];
                    }
                    *reinterpret_cast<float4*>(sZ + i * HSTR + fgl) = make_float4(zz[0], zz[1], zz[2], zz[3]);
                    *reinterpret_cast<float4*>(sHR + i * HSTR + fgl) = make_float4(rr[0], rr[1], rr[2], rr[3]);
                    u32 la = smem_u32(sHR + i * HSTR + fgl);
                    st_peer_u64(la, peer, pk2(rr[0], rr[1]));
                    st_peer_u64(la + 8, peer, pk2(rr[2], rr[3]));
                }
            }
        }
        CLUSTER_ARRIVE();   // HR exchanged
        CLUSTER_WAIT();

        // ---- P2: Ht1 + blend into H1 (S = full HR) ----
        {
            u64 A[1][3][2] = {};
            run_pass<1>(sHR, Vh1, nullptr, sw, tid, kh, i0, ui, A);
            if (tid < 128) {
#pragma unroll
                for (int r = 0; r < 3; r++) {
                    int i = i0 + r; float yv = sy[i];
                    float v[4];
                    up2(A[0][r][0], v[0], v[1]); up2(A[0][r][1], v[2], v[3]);
                    float4 h4 = *reinterpret_cast<const float4*>(sH1 + i * HSTR + fgl);
                    float4 z4 = *reinterpret_cast<const float4*>(sZ + i * HSTR + fgl);
                    float h[4] = {h4.x, h4.y, h4.z, h4.w};
                    float z[4] = {z4.x, z4.y, z4.z, z4.w};
                    float nh[4];
#pragma unroll
                    for (int c = 0; c < 4; c++) {
                        int f = fgl + c;
                        float hh = tanh_(fmaf(yv, svh[f], sch[f]) + v[c]);
                        nh[c] = fmaf(z[c], h[c] - hh, hh);
                    }
                    *reinterpret_cast<float4*>(sH1 + i * HSTR + fgl) = make_float4(nh[0], nh[1], nh[2], nh[3]);
                    u32 la = smem_u32(sH1 + i * HSTR + fgl);
                    st_peer_u64(la, peer, pk2(nh[0], nh[1]));
                    st_peer_u64(la + 8, peer, pk2(nh[2], nh[3]));
                }
            }
        }
        CLUSTER_ARRIVE();   // H1 exchanged
        CLUSTER_WAIT();

        // ---- P3: Mz, Mr = H1 @ W2L{z,r} (local half output) ----
        {
            u64 A[2][3][2] = {};
            run_pass<2>(sH1, W2Lz, W2Lr, sw, tid, kh, i0, ui, A);
            if (tid < 128) {
#pragma unroll
                for (int r = 0; r < 3; r++) {
                    int i = i0 + r;
                    float a[4], bq[4];
                    up2(A[0][r][0], a[0], a[1]); up2(A[0][r][1], a[2], a[3]);
                    up2(A[1][r][0], bq[0], bq[1]); up2(A[1][r][1], bq[2], bq[3]);
                    *reinterpret_cast<float4*>(sMa + i * HSTR + f0) = make_float4(a[0], a[1], a[2], a[3]);
                    *reinterpret_cast<float4*>(sMb + i * HSTR + f0) = make_float4(bq[0], bq[1], bq[2], bq[3]);
                }
            }
        }

        // ---- P4: Mh = H1 @ W2Lh ----
        {
            u64 A[1][3][2] = {};
            run_pass<1>(sH1, W2Lh, nullptr, sw, tid, kh, i0, ui, A);
            if (tid < 128) {
#pragma unroll
                for (int r = 0; r < 3; r++) {
                    int i = i0 + r;
                    float a[4];
                    up2(A[0][r][0], a[0], a[1]); up2(A[0][r][1], a[2], a[3]);
                    *reinterpret_cast<float4*>(sMc + i * HSTR + f0) = make_float4(a[0], a[1], a[2], a[3]);
                }
            }
        }

        // ---- P5: Z2 / R2 (bias + split amix + H2 matmul; S = full H2) ----
        {
            u64 A[2][3][2];
            if (kh == 0) {
                u64 cz0 = pk2(sc2z[fgl], sc2z[fgl + 1]), cz1 = pk2(sc2z[fgl + 2], sc2z[fgl + 3]);
                u64 cr0 = pk2(sc2r[fgl], sc2r[fgl + 1]), cr1 = pk2(sc2r[fgl + 2], sc2r[fgl + 3]);
#pragma unroll
                for (int r = 0; r < 3; r++) {
                    A[0][r][0] = cz0; A[0][r][1] = cz1;
                    A[1][r][0] = cr0; A[1][r][1] = cr1;
                }
                amixN<2>(sA, sMa, sMb, 0, 11, i0, ui, A);
            } else {
#pragma unroll
                for (int r = 0; r < 3; r++) {
                    A[0][r][0] = 0; A[0][r][1] = 0;
                    A[1][r][0] = 0; A[1][r][1] = 0;
                }
                amixN<2>(sA, sMa, sMb, 11, NNODE, i0, ui, A);
            }
            run_pass<2>(sH2, Vz2, Vr2, sw, tid, kh, i0, ui, A);
            if (tid < 128) {
#pragma unroll
                for (int r = 0; r < 3; r++) {
                    int i = i0 + r;
                    float v[4], q[4];
                    up2(A[0][r][0], v[0], v[1]); up2(A[0][r][1], v[2], v[3]);
                    up2(A[1][r][0], q[0], q[1]); up2(A[1][r][1], q[2], q[3]);
                    float4 h4 = *reinterpret_cast<const float4*>(sH2 + i * HSTR + fgl);
                    float h[4] = {h4.x, h4.y, h4.z, h4.w};
                    float zz[4], rr[4];
#pragma unroll
                    for (int c = 0; c < 4; c++) {
                        zz[c] = sigm(v[c]);
                        rr[c] = sigm(q[c]) * h[c];
                    }
                    *reinterpret_cast<float4*>(sZ + i * HSTR + fgl) = make_float4(zz[0], zz[1], zz[2], zz[3]);
                    *reinterpret_cast<float4*>(sHR + i * HSTR + fgl) = make_float4(rr[0], rr[1], rr[2], rr[3]);
                    u32 la = smem_u32(sHR + i * HSTR + fgl);
                    st_peer_u64(la, peer, pk2(rr[0], rr[1]));
                    st_peer_u64(la + 8, peer, pk2(rr[2], rr[3]));
                }
            }
        }
        CLUSTER_ARRIVE();   // HR2 exchanged
        CLUSTER_WAIT();

        // ---- P6: Ht2 + blend into H2 + output accumulation (S = full HR) ----
        {
            u64 A[1][3][2];
            if (kh == 0) {
                u64 ch0 = pk2(sc2h[fgl], sc2h[fgl + 1]), ch1 = pk2(sc2h[fgl + 2], sc2h[fgl + 3]);
#pragma unroll
                for (int r = 0; r < 3; r++) { A[0][r][0] = ch0; A[0][r][1] = ch1; }
                amixN<1>(sA, sMc, nullptr, 0, 11, i0, ui, A);
            } else {
#pragma unroll
                for (int r = 0; r < 3; r++) { A[0][r][0] = 0; A[0][r][1] = 0; }
                amixN<1>(sA, sMc, nullptr, 11, NNODE, i0, ui, A);
            }
            run_pass<1>(sHR, Vh2, nullptr, sw, tid, kh, i0, ui, A);
            if (tid < 128) {
#pragma unroll
                for (int r = 0; r < 3; r++) {
                    int i = i0 + r;
                    float v[4];
                    up2(A[0][r][0], v[0], v[1]); up2(A[0][r][1], v[2], v[3]);
                    float4 h4 = *reinterpret_cast<const float4*>(sH2 + i * HSTR + fgl);
                    float4 z4 = *reinterpret_cast<const float4*>(sZ + i * HSTR + fgl);
                    float h[4] = {h4.x, h4.y, h4.z, h4.w};
                    float z[4] = {z4.x, z4.y, z4.z, z4.w};
                    float nh[4];
#pragma unroll
                    for (int c = 0; c < 4; c++) {
                        float hh = tanh_(v[c]);
                        nh[c] = fmaf(z[c], h[c] - hh, hh);
                        if (rg < 7) accS[r * 4 + c] += nh[c];
                    }
                    *reinterpret_cast<float4*>(sH2 + i * HSTR + fgl) = make_float4(nh[0], nh[1], nh[2], nh[3]);
                    u32 la = smem_u32(sH2 + i * HSTR + fgl);
                    st_peer_u64(la, peer, pk2(nh[0], nh[1]));
                    st_peer_u64(la + 8, peer, pk2(nh[2], nh[3]));
                }
            }
        }
        CLUSTER_ARRIVE();   // H2 exchanged (consumed next step P5)
    }
    CLUSTER_WAIT();          // matches last arrive

    // ---- final: partial over own 64 features; combine across cluster ----
    __syncthreads();
    if (tid < 128 && rg < 7) {
        float cs[4];
#pragma unroll
        for (int c = 0; c < 4; c++) cs[c] = accS[c] + accS[4 + c] + accS[8 + c];
        *reinterpret_cast<float4*>(sMa + rg * FHALF + f0) = make_float4(cs[0], cs[1], cs[2], cs[3]);
    }
    __syncthreads();
    if (tid < FHALF) {
        float s = 0.f;
#pragma unroll
        for (int r = 0; r < 7; r++) s += sMa[r * FHALF + tid];
        s *= (1.0f / (float)(NNODE * TSTEPS));
        sMb[tid] = s * clsw[rank * FHALF + tid];
    }
    __syncthreads();
    float own = 0.f;
    if (tid == 0) {
        for (int f = 0; f < FHALF; f++) own += sMb[f];
        if (rank == 1) st_peer_u32(smem_u32(sy + 24), 0, __float_as_uint(own));
    }
    CLUSTER_ARRIVE();
    CLUSTER_WAIT();
    if (rank == 0 && tid == 0)
        out[b] = own + sy[24] + clsb[0];
}

// ---------------- launch ----------------
extern "C" void kernel_launch(void* const* d_in, const int* in_sizes, int n_in,
                              void* d_out, int out_size) {
    const float* x    = (const float*)d_in[0];
    const int*   ei   = (const int*)d_in[1];
    const float* ew   = (const float*)d_in[2];
    const float* Wz1  = (const float*)d_in[3];
    const float* bz1  = (const float*)d_in[4];
    const float* lzw1 = (const float*)d_in[5];
    const float* lzb1 = (const float*)d_in[6];
    const float* Wr1  = (const float*)d_in[7];
    const float* br1  = (const float*)d_in[8];
    const float* lrw1 = (const float*)d_in[9];
    const float* lrb1 = (const float*)d_in[10];
    const float* Wh1  = (const float*)d_in[11];
    const float* bh1  = (const float*)d_in[12];
    const float* lhw1 = (const float*)d_in[13];
    const float* lhb1 = (const float*)d_in[14];
    const float* Wz2  = (const float*)d_in[15];
    const float* bz2  = (const float*)d_in[16];
    const float* lzw2 = (const float*)d_in[17];
    const float* lzb2 = (const float*)d_in[18];
    const float* Wr2  = (const float*)d_in[19];
    const float* br2  = (const float*)d_in[20];
    const float* lrw2 = (const float*)d_in[21];
    const float* lrb2 = (const float*)d_in[22];
    const float* Wh2  = (const float*)d_in[23];
    const float* bh2  = (const float*)d_in[24];
    const float* lhw2 = (const float*)d_in[25];
    const float* lhb2 = (const float*)d_in[26];
    const float* clsw = (const float*)d_in[27];
    const float* clsb = (const float*)d_in[28];
    float* out = (float*)d_out;

    setup_all<<<385, 448>>>(ei, ew,
        Wz1, bz1, lzw1, lzb1, Wr1, br1, lrw1, lrb1, Wh1, bh1, lhw1, lhb1,
        Wz2, bz2, lzw2, lzb2, Wr2, br2, lrw2, lrb2, Wh2, bh2, lhw2, lhb2);

    const int smem_bytes = SMEM_FLOATS * (int)sizeof(float);  // 160992
    cudaFuncSetAttribute(tgcn_main, cudaFuncAttributeMaxDynamicSharedMemorySize, smem_bytes);
    tgcn_main<<<128, NTHR, smem_bytes>>>(
        x,
        lzw1 + HIDD * HIDD, lrw1 + HIDD * HIDD, lhw1 + HIDD * HIDD,
        lzw2 + HIDD * HIDD, lrw2 + HIDD * HIDD, lhw2 + HIDD * HIDD,
        clsw, clsb, out);
}